// round 9
// baseline (speedup 1.0000x reference)
#include <cuda_runtime.h>
#include <cuda_bf16.h>
#include <math.h>
#include <stdint.h>

// Problem constants
#define NP_   1024
#define MNP_  4096
#define BS_   4
#define DIM_  512
#define NH_   8
#define DH_   64
#define TOPK_ 32

#define MROWS_Q  (NP_*BS_)                 // 4096
#define MROWS_KV (MNP_*BS_)                // 16384
#define MTOT     (MROWS_Q + 2*MROWS_KV)    // 36864

// ---------------------------------------------------------------------------
// Scratch (device globals; no allocation allowed)
// ---------------------------------------------------------------------------
__device__ __nv_bfloat16 g_ahi[(size_t)MTOT * DIM_];
__device__ __nv_bfloat16 g_alo[(size_t)MTOT * DIM_];
__device__ __nv_bfloat16 g_whi[3 * DIM_ * DIM_];
__device__ __nv_bfloat16 g_wlo[3 * DIM_ * DIM_];
__device__ float         g_proj[(size_t)MTOT * DIM_];

// ---------------------------------------------------------------------------
// Helpers
// ---------------------------------------------------------------------------
__device__ __forceinline__ uint32_t smem_u32(const void* p) {
    uint32_t a;
    asm("{ .reg .u64 t; cvta.to.shared.u64 t, %1; cvt.u32.u64 %0, t; }"
        : "=r"(a) : "l"(p));
    return a;
}

__device__ __forceinline__ void cp16(uint32_t dst, const void* src) {
    asm volatile("cp.async.cg.shared.global [%0], [%1], 16;\n"
                 :: "r"(dst), "l"(src) : "memory");
}

__device__ __forceinline__ uint32_t swz(uint32_t o) { return o ^ ((o >> 3) & 0x70); }

__device__ __forceinline__ void ldsm4(uint32_t* f, uint32_t addr) {
    asm volatile("ldmatrix.sync.aligned.m8n8.x4.shared.b16 {%0,%1,%2,%3}, [%4];"
                 : "=r"(f[0]), "=r"(f[1]), "=r"(f[2]), "=r"(f[3]) : "r"(addr));
}

__device__ __forceinline__ void mma16816(float* d, const uint32_t* a,
                                         const uint32_t* b) {
    asm volatile(
        "mma.sync.aligned.m16n8k16.row.col.f32.bf16.bf16.f32 "
        "{%0,%1,%2,%3}, {%4,%5,%6,%7}, {%8,%9}, {%0,%1,%2,%3};"
        : "+f"(d[0]), "+f"(d[1]), "+f"(d[2]), "+f"(d[3])
        : "r"(a[0]), "r"(a[1]), "r"(a[2]), "r"(a[3]), "r"(b[0]), "r"(b[1]));
}

// ---------------------------------------------------------------------------
// Fused split: fp32 -> (bf16 hi, bf16 lo); q|k|v -> g_ahi/g_alo and
// W1|W2|W3 -> g_whi/g_wlo. Each thread handles 2 consecutive float4s.
// ---------------------------------------------------------------------------
#define R_Q  (MROWS_Q * DIM_ / 4)                 // 524288
#define R_K  (R_Q + MROWS_KV * DIM_ / 4)          // 2621440
#define R_V  (R_K + MROWS_KV * DIM_ / 4)          // 4718592
#define R_W1 (R_V + DIM_ * DIM_ / 4)
#define R_W2 (R_W1 + DIM_ * DIM_ / 4)
#define R_W3 (R_W2 + DIM_ * DIM_ / 4)             // 4915200 total

__global__ __launch_bounds__(256)
void split_all(const float* __restrict__ q, const float* __restrict__ k,
               const float* __restrict__ v, const float* __restrict__ W1,
               const float* __restrict__ W2, const float* __restrict__ W3,
               __nv_bfloat16* __restrict__ ahi, __nv_bfloat16* __restrict__ alo,
               __nv_bfloat16* __restrict__ whi, __nv_bfloat16* __restrict__ wlo) {
    const int i = (blockIdx.x * 256 + threadIdx.x) * 2;   // float4 index
    if (i >= R_W3) return;
    const float* src;
    __nv_bfloat16 *dh, *dl;
    size_t si, di;
    if (i < R_V) {
        di = (size_t)i;
        dh = ahi; dl = alo;
        if (i < R_Q)      { src = q; si = (size_t)i; }
        else if (i < R_K) { src = k; si = (size_t)(i - R_Q); }
        else              { src = v; si = (size_t)(i - R_K); }
    } else {
        di = (size_t)(i - R_V);
        dh = whi; dl = wlo;
        if (i < R_W1)      { src = W1; si = (size_t)(i - R_V); }
        else if (i < R_W2) { src = W2; si = (size_t)(i - R_W1); }
        else               { src = W3; si = (size_t)(i - R_W2); }
    }
    float4 x0 = ((const float4*)src)[si];
    float4 x1 = ((const float4*)src)[si + 1];
    float val[8] = {x0.x, x0.y, x0.z, x0.w, x1.x, x1.y, x1.z, x1.w};
    __nv_bfloat16 h[8], l[8];
#pragma unroll
    for (int j = 0; j < 8; j++) {
        h[j] = __float2bfloat16(val[j]);
        l[j] = __float2bfloat16(val[j] - __bfloat162float(h[j]));
    }
    *(uint4*)(dh + 4 * di) = *(uint4*)h;
    *(uint4*)(dl + 4 * di) = *(uint4*)l;
}

// ---------------------------------------------------------------------------
// mma.sync split-bf16 GEMM: out = A*W^T + bias
// CTA tile 128x128, K-chunk 64, 3-stage cp.async pipeline.
// 4 warps (128 threads) as 2(m) x 2(n): warp tile 64x64 -> per k16-step
// 8 ldmatrix.x4 feed 32 HMMAs (MMA:LDSM = 4:1).
// ---------------------------------------------------------------------------
#define KC       64
#define NCHUNK   24
#define STAGES   3
#define A_BYTES  (128 * 128)
#define B_BYTES  (128 * 128)
#define STG_B    (A_BYTES + B_BYTES)
#define GEMM_SMEM (STAGES * STG_B)           // 96KB

__global__ __launch_bounds__(128)
void gemm_mma(const __nv_bfloat16* __restrict__ ahi,
              const __nv_bfloat16* __restrict__ alo,
              const __nv_bfloat16* __restrict__ whi,
              const __nv_bfloat16* __restrict__ wlo,
              const float* __restrict__ b1, const float* __restrict__ b2,
              const float* __restrict__ b3, float* __restrict__ out) {
    extern __shared__ __align__(1024) char smem[];
    const uint32_t sbase = smem_u32(smem);
    const int tid = threadIdx.x;
    const int wid = tid >> 5;
    const int lane = tid & 31;
    const int wm = wid & 1;                 // m half
    const int wn = wid >> 1;                // n half

    const int n0blk = blockIdx.x * 128;
    const int mt = blockIdx.y;
    const int widx = (mt < 32) ? 0 : (mt < 160) ? 1 : 2;
    const float* bias = (widx == 0) ? b1 : (widx == 1) ? b2 : b3;
    const __nv_bfloat16* Whi = whi + (size_t)widx * DIM_ * DIM_;
    const __nv_bfloat16* Wlo = wlo + (size_t)widx * DIM_ * DIM_;
    const size_t arow0 = (size_t)mt * 128;

    float acc[4][8][4];
#pragma unroll
    for (int i = 0; i < 4; i++)
#pragma unroll
        for (int j = 0; j < 8; j++)
#pragma unroll
            for (int r = 0; r < 4; r++) acc[i][j][r] = 0.f;

    // chunk c: term t = c>>3 (0:hi*Whi, 1:hi*Wlo, 2:lo*Whi), k-off = (c&7)*64
    auto load_chunk = [&](int c, int s) {
        const int t  = c >> 3;
        const int kk = (c & 7) * KC;
        const __nv_bfloat16* Ap = (t < 2) ? ahi : alo;
        const __nv_bfloat16* Bp = (t == 1) ? Wlo : Whi;
        const uint32_t a_s = sbase + s * STG_B;
        const uint32_t b_s = a_s + A_BYTES;
#pragma unroll
        for (int i = 0; i < 8; i++) {        // A: 1024 16B units, 128 thr
            int u = tid + (i << 7);
            int r = u >> 3, j = u & 7;
            cp16(a_s + swz(r * 128 + j * 16),
                 Ap + (arow0 + r) * DIM_ + kk + j * 8);
        }
#pragma unroll
        for (int i = 0; i < 8; i++) {        // B: 1024 16B units
            int u = tid + (i << 7);
            int r = u >> 3, j = u & 7;
            cp16(b_s + swz(r * 128 + j * 16),
                 Bp + (size_t)(n0blk + r) * DIM_ + kk + j * 8);
        }
        asm volatile("cp.async.commit_group;\n" ::: "memory");
    };

    load_chunk(0, 0);
    load_chunk(1, 1);

    const int a_row = wm * 64 + (lane & 15);          // + i*16
    const int a_ch  = (lane >> 4);                    // + c0
    const int b_row = wn * 64 + (lane & 7) + ((lane >> 4) << 3);  // + j*16
    const int b_ch  = ((lane >> 3) & 1);              // + c0

#pragma unroll 1
    for (int c = 0; c < NCHUNK; ++c) {
        const int s = c % STAGES;
        if (c == NCHUNK - 1)
            asm volatile("cp.async.wait_group 0;\n" ::: "memory");
        else
            asm volatile("cp.async.wait_group 1;\n" ::: "memory");
        __syncthreads();
        if (c + 2 < NCHUNK) load_chunk(c + 2, (c + 2) % STAGES);

        const uint32_t a_s = sbase + s * STG_B;
        const uint32_t b_s = a_s + A_BYTES;
#pragma unroll
        for (int ks = 0; ks < 4; ks++) {
            const int c0 = ks * 2;
            uint32_t af[4][4];
#pragma unroll
            for (int i = 0; i < 4; i++)
                ldsm4(af[i], a_s + swz((a_row + i * 16) * 128 + (c0 + a_ch) * 16));
            uint32_t bf[4][4];                   // [j]: n-tiles 2j, 2j+1
#pragma unroll
            for (int j = 0; j < 4; j++)
                ldsm4(bf[j], b_s + swz((b_row + j * 16) * 128 + (c0 + b_ch) * 16));
#pragma unroll
            for (int i = 0; i < 4; i++)
#pragma unroll
                for (int j = 0; j < 4; j++) {
                    mma16816(acc[i][2 * j],     af[i], &bf[j][0]);
                    mma16816(acc[i][2 * j + 1], af[i], &bf[j][2]);
                }
        }
    }

    // epilogue: acc[i][j] is m16n8 at rows (wm*64+i*16), cols (wn*64+j*8)
    const int lr = lane >> 2;
    const int lc = (lane & 3) * 2;
#pragma unroll
    for (int i = 0; i < 4; i++) {
        const size_t row0 = arow0 + wm * 64 + i * 16 + lr;
#pragma unroll
        for (int j = 0; j < 8; j++) {
            const int col = n0blk + wn * 64 + j * 8 + lc;
            const float bx = bias[col], by = bias[col + 1];
            float2 o0 = make_float2(acc[i][j][0] + bx, acc[i][j][1] + by);
            float2 o1 = make_float2(acc[i][j][2] + bx, acc[i][j][3] + by);
            *(float2*)(out + row0 * DIM_ + col) = o0;
            *(float2*)(out + (row0 + 8) * DIM_ + col) = o1;
        }
    }
}

// ---------------------------------------------------------------------------
// Sparse attention (R8 version, unchanged).
// ---------------------------------------------------------------------------
__global__ __launch_bounds__(256)
void attn_kernel(const float* __restrict__ qh, const float* __restrict__ kh,
                 const float* __restrict__ vh, const int* __restrict__ rns,
                 float* __restrict__ out) {
    __shared__ float sq[DIM_];
    __shared__ int srow[TOPK_];
    __shared__ int svrow[TOPK_];
    __shared__ float sscore[NH_][TOPK_];

    const int n = blockIdx.x;
    const int b = blockIdx.y;
    const int tid = threadIdx.x;
    const int lane = tid & 31;
    const int wid = tid >> 5;

    ((float2*)sq)[tid] = ((const float2*)(qh + (size_t)(n * BS_ + b) * DIM_))[tid];
    if (tid < TOPK_)
        srow[tid] = rns[((size_t)b * NP_ + n) * TOPK_ + tid];
    __syncthreads();
    if (tid < TOPK_) {
        const int m = srow[tid];
        bool valid = true;
        for (int j = 0; j < tid; j++)
            if (srow[j] == m) valid = false;
        svrow[tid] = valid ? (m * BS_ + b) : -1;
    }
    __syncthreads();

    // ---- Phase 1: scores (warp w covers candidates w, w+8, w+16, w+24) ----
    const int g = lane >> 4;
#pragma unroll
    for (int cc = 0; cc < 4; cc++) {
        const int c = wid + cc * 8;
        const int r = svrow[c];
        float p[4] = {0.f, 0.f, 0.f, 0.f};
        if (r >= 0) {
            const float4* kp = (const float4*)(kh + (size_t)r * DIM_);
            const float4* qp = (const float4*)sq;
#pragma unroll
            for (int j = 0; j < 4; j++) {
                const float4 kv = kp[j * 32 + lane];
                const float4 qv = qp[j * 32 + lane];
                float a;
                a = kv.x * qv.x;
                a = fmaf(kv.y, qv.y, a);
                a = fmaf(kv.z, qv.z, a);
                a = fmaf(kv.w, qv.w, a);
                p[j] = a;
            }
        }
#pragma unroll
        for (int j = 0; j < 4; j++) {
            p[j] += __shfl_xor_sync(0xffffffffu, p[j], 8);
            p[j] += __shfl_xor_sync(0xffffffffu, p[j], 4);
            p[j] += __shfl_xor_sync(0xffffffffu, p[j], 2);
            p[j] += __shfl_xor_sync(0xffffffffu, p[j], 1);
        }
        if ((lane & 15) == 0) {
#pragma unroll
            for (int j = 0; j < 4; j++)
                sscore[2 * j + g][c] = (r >= 0) ? p[j] * 0.125f : -INFINITY;
        }
    }
    __syncthreads();

    // ---- Phase 2: per-head softmax ----
    const int h = wid;
    const float s = sscore[h][lane];
    float mx = s;
#pragma unroll
    for (int o = 16; o; o >>= 1)
        mx = fmaxf(mx, __shfl_xor_sync(0xffffffffu, mx, o));
    float p = (s > -1e30f) ? __expf(s - mx) : 0.f;
    float sum = p;
#pragma unroll
    for (int o = 16; o; o >>= 1)
        sum += __shfl_xor_sync(0xffffffffu, sum, o);
    const float w = p / sum;

    // ---- Phase 3: V accumulate ----
    const int rl = svrow[lane];
    float2 acc2 = make_float2(0.f, 0.f);
#pragma unroll
    for (int t = 0; t < TOPK_; t++) {
        const float wt = __shfl_sync(0xffffffffu, w, t);
        const int r = __shfl_sync(0xffffffffu, rl, t);
        if (r >= 0) {
            const float2 vv =
                *(const float2*)(vh + (size_t)r * DIM_ + h * DH_ + lane * 2);
            acc2.x = fmaf(wt, vv.x, acc2.x);
            acc2.y = fmaf(wt, vv.y, acc2.y);
        }
    }
    *(float2*)(out + (size_t)(n * BS_ + b) * DIM_ + h * DH_ + lane * 2) = acc2;
}

// ---------------------------------------------------------------------------
extern "C" void kernel_launch(void* const* d_in, const int* in_sizes, int n_in,
                              void* d_out, int out_size) {
    const float* q   = (const float*)d_in[0];
    const float* k   = (const float*)d_in[1];
    const float* v   = (const float*)d_in[2];
    const int*   rns = (const int*)d_in[3];
    const float* W1  = (const float*)d_in[4];
    const float* b1  = (const float*)d_in[5];
    const float* W2  = (const float*)d_in[6];
    const float* b2  = (const float*)d_in[7];
    const float* W3  = (const float*)d_in[8];
    const float* b3  = (const float*)d_in[9];
    float* out = (float*)d_out;

    __nv_bfloat16 *ahi, *alo, *whi, *wlo;
    float* proj;
    cudaGetSymbolAddress((void**)&ahi, g_ahi);
    cudaGetSymbolAddress((void**)&alo, g_alo);
    cudaGetSymbolAddress((void**)&whi, g_whi);
    cudaGetSymbolAddress((void**)&wlo, g_wlo);
    cudaGetSymbolAddress((void**)&proj, g_proj);

    cudaFuncSetAttribute(gemm_mma, cudaFuncAttributeMaxDynamicSharedMemorySize,
                         GEMM_SMEM);

    const size_t offK = (size_t)MROWS_Q * DIM_;
    const size_t offV = offK + (size_t)MROWS_KV * DIM_;

    split_all<<<(R_W3 / 2 + 255) / 256, 256>>>(q, k, v, W1, W2, W3,
                                               ahi, alo, whi, wlo);

    gemm_mma<<<dim3(4, 288), 128, GEMM_SMEM>>>(ahi, alo, whi, wlo, b1, b2, b3, proj);

    attn_kernel<<<dim3(NP_, BS_), 256>>>(proj, proj + offK, proj + offV, rns, out);
}

// round 11
// speedup vs baseline: 1.0684x; 1.0684x over previous
#include <cuda_runtime.h>
#include <cuda_bf16.h>
#include <math.h>
#include <stdint.h>

// Problem constants
#define NP_   1024
#define MNP_  4096
#define BS_   4
#define DIM_  512
#define NH_   8
#define DH_   64
#define TOPK_ 32

#define MROWS_Q  (NP_*BS_)                 // 4096
#define MROWS_KV (MNP_*BS_)                // 16384
#define MTOT     (MROWS_Q + 2*MROWS_KV)    // 36864

// ---------------------------------------------------------------------------
// Scratch (device globals; no allocation allowed)
// ---------------------------------------------------------------------------
__device__ __nv_bfloat16 g_ahi[(size_t)MTOT * DIM_];
__device__ __nv_bfloat16 g_alo[(size_t)MTOT * DIM_];
__device__ __nv_bfloat16 g_whi[3 * DIM_ * DIM_];
__device__ __nv_bfloat16 g_wlo[3 * DIM_ * DIM_];
__device__ float         g_proj[(size_t)MTOT * DIM_];

// ---------------------------------------------------------------------------
// Helpers
// ---------------------------------------------------------------------------
__device__ __forceinline__ uint32_t smem_u32(const void* p) {
    uint32_t a;
    asm("{ .reg .u64 t; cvta.to.shared.u64 t, %1; cvt.u32.u64 %0, t; }"
        : "=r"(a) : "l"(p));
    return a;
}

__device__ __forceinline__ void cp16(uint32_t dst, const void* src) {
    asm volatile("cp.async.cg.shared.global [%0], [%1], 16;\n"
                 :: "r"(dst), "l"(src) : "memory");
}

__device__ __forceinline__ uint32_t swz(uint32_t o) { return o ^ ((o >> 3) & 0x70); }

__device__ __forceinline__ void ldsm4(uint32_t* f, uint32_t addr) {
    asm volatile("ldmatrix.sync.aligned.m8n8.x4.shared.b16 {%0,%1,%2,%3}, [%4];"
                 : "=r"(f[0]), "=r"(f[1]), "=r"(f[2]), "=r"(f[3]) : "r"(addr));
}

__device__ __forceinline__ void mma16816(float* d, const uint32_t* a,
                                         const uint32_t* b) {
    asm volatile(
        "mma.sync.aligned.m16n8k16.row.col.f32.bf16.bf16.f32 "
        "{%0,%1,%2,%3}, {%4,%5,%6,%7}, {%8,%9}, {%0,%1,%2,%3};"
        : "+f"(d[0]), "+f"(d[1]), "+f"(d[2]), "+f"(d[3])
        : "r"(a[0]), "r"(a[1]), "r"(a[2]), "r"(a[3]), "r"(b[0]), "r"(b[1]));
}

// ---------------------------------------------------------------------------
// Fused split: fp32 -> (bf16 hi, bf16 lo); q|k|v -> g_ahi/g_alo and
// W1|W2|W3 -> g_whi/g_wlo. Each thread handles 2 consecutive float4s.
// ---------------------------------------------------------------------------
#define R_Q  (MROWS_Q * DIM_ / 4)                 // 524288
#define R_K  (R_Q + MROWS_KV * DIM_ / 4)          // 2621440
#define R_V  (R_K + MROWS_KV * DIM_ / 4)          // 4718592
#define R_W1 (R_V + DIM_ * DIM_ / 4)
#define R_W2 (R_W1 + DIM_ * DIM_ / 4)
#define R_W3 (R_W2 + DIM_ * DIM_ / 4)             // 4915200 total

__global__ __launch_bounds__(256)
void split_all(const float* __restrict__ q, const float* __restrict__ k,
               const float* __restrict__ v, const float* __restrict__ W1,
               const float* __restrict__ W2, const float* __restrict__ W3,
               __nv_bfloat16* __restrict__ ahi, __nv_bfloat16* __restrict__ alo,
               __nv_bfloat16* __restrict__ whi, __nv_bfloat16* __restrict__ wlo) {
    const int i = (blockIdx.x * 256 + threadIdx.x) * 2;   // float4 index
    if (i >= R_W3) return;
    const float* src;
    __nv_bfloat16 *dh, *dl;
    size_t si, di;
    if (i < R_V) {
        di = (size_t)i;
        dh = ahi; dl = alo;
        if (i < R_Q)      { src = q; si = (size_t)i; }
        else if (i < R_K) { src = k; si = (size_t)(i - R_Q); }
        else              { src = v; si = (size_t)(i - R_K); }
    } else {
        di = (size_t)(i - R_V);
        dh = whi; dl = wlo;
        if (i < R_W1)      { src = W1; si = (size_t)(i - R_V); }
        else if (i < R_W2) { src = W2; si = (size_t)(i - R_W1); }
        else               { src = W3; si = (size_t)(i - R_W2); }
    }
    float4 x0 = ((const float4*)src)[si];
    float4 x1 = ((const float4*)src)[si + 1];
    float val[8] = {x0.x, x0.y, x0.z, x0.w, x1.x, x1.y, x1.z, x1.w};
    __nv_bfloat16 h[8], l[8];
#pragma unroll
    for (int j = 0; j < 8; j++) {
        h[j] = __float2bfloat16(val[j]);
        l[j] = __float2bfloat16(val[j] - __bfloat162float(h[j]));
    }
    *(uint4*)(dh + 4 * di) = *(uint4*)h;
    *(uint4*)(dl + 4 * di) = *(uint4*)l;
}

// ---------------------------------------------------------------------------
// mma.sync split-bf16 GEMM (R8 layout: 8 warps, 32x64 warp tile), with
// __launch_bounds__(256, 2) to guarantee 2 CTAs/SM (128-reg cap).
// ---------------------------------------------------------------------------
#define KC       64
#define NCHUNK   24
#define STAGES   3
#define A_BYTES  (128 * 128)
#define B_BYTES  (128 * 128)
#define STG_B    (A_BYTES + B_BYTES)
#define GEMM_SMEM (STAGES * STG_B)           // 96KB

__global__ __launch_bounds__(256, 2)
void gemm_mma(const __nv_bfloat16* __restrict__ ahi,
              const __nv_bfloat16* __restrict__ alo,
              const __nv_bfloat16* __restrict__ whi,
              const __nv_bfloat16* __restrict__ wlo,
              const float* __restrict__ b1, const float* __restrict__ b2,
              const float* __restrict__ b3, float* __restrict__ out) {
    extern __shared__ __align__(1024) char smem[];
    const uint32_t sbase = smem_u32(smem);
    const int tid = threadIdx.x;
    const int wid = tid >> 5;
    const int lane = tid & 31;
    const int wm = wid & 3;
    const int wn = wid >> 2;

    const int n0blk = blockIdx.x * 128;
    const int mt = blockIdx.y;
    const int widx = (mt < 32) ? 0 : (mt < 160) ? 1 : 2;
    const float* bias = (widx == 0) ? b1 : (widx == 1) ? b2 : b3;
    const __nv_bfloat16* Whi = whi + (size_t)widx * DIM_ * DIM_;
    const __nv_bfloat16* Wlo = wlo + (size_t)widx * DIM_ * DIM_;
    const size_t arow0 = (size_t)mt * 128;

    float acc[2][8][4];
#pragma unroll
    for (int i = 0; i < 2; i++)
#pragma unroll
        for (int j = 0; j < 8; j++)
#pragma unroll
            for (int r = 0; r < 4; r++) acc[i][j][r] = 0.f;

    auto load_chunk = [&](int c, int s) {
        const int t  = c >> 3;
        const int kk = (c & 7) * KC;
        const __nv_bfloat16* Ap = (t < 2) ? ahi : alo;
        const __nv_bfloat16* Bp = (t == 1) ? Wlo : Whi;
        const uint32_t a_s = sbase + s * STG_B;
        const uint32_t b_s = a_s + A_BYTES;
#pragma unroll
        for (int i = 0; i < 4; i++) {
            int u = tid + (i << 8);
            int r = u >> 3, j = u & 7;
            cp16(a_s + swz(r * 128 + j * 16),
                 Ap + (arow0 + r) * DIM_ + kk + j * 8);
        }
#pragma unroll
        for (int i = 0; i < 4; i++) {
            int u = tid + (i << 8);
            int r = u >> 3, j = u & 7;
            cp16(b_s + swz(r * 128 + j * 16),
                 Bp + (size_t)(n0blk + r) * DIM_ + kk + j * 8);
        }
        asm volatile("cp.async.commit_group;\n" ::: "memory");
    };

    load_chunk(0, 0);
    load_chunk(1, 1);

    const int a_row = wm * 32 + (lane & 15);
    const int a_ch  = (lane >> 4);
    const int b_row = wn * 64 + (lane & 7) + ((lane >> 4) << 3);
    const int b_ch  = ((lane >> 3) & 1);

#pragma unroll 1
    for (int c = 0; c < NCHUNK; ++c) {
        const int s = c % STAGES;
        if (c == NCHUNK - 1)
            asm volatile("cp.async.wait_group 0;\n" ::: "memory");
        else
            asm volatile("cp.async.wait_group 1;\n" ::: "memory");
        __syncthreads();
        if (c + 2 < NCHUNK) load_chunk(c + 2, (c + 2) % STAGES);

        const uint32_t a_s = sbase + s * STG_B;
        const uint32_t b_s = a_s + A_BYTES;
#pragma unroll
        for (int ks = 0; ks < 4; ks++) {
            const int c0 = ks * 2;
            uint32_t af[2][4];
#pragma unroll
            for (int i = 0; i < 2; i++)
                ldsm4(af[i], a_s + swz((a_row + i * 16) * 128 + (c0 + a_ch) * 16));
            uint32_t bf[4][4];
#pragma unroll
            for (int j = 0; j < 4; j++)
                ldsm4(bf[j], b_s + swz((b_row + j * 16) * 128 + (c0 + b_ch) * 16));
#pragma unroll
            for (int i = 0; i < 2; i++)
#pragma unroll
                for (int j = 0; j < 4; j++) {
                    mma16816(acc[i][2 * j],     af[i], &bf[j][0]);
                    mma16816(acc[i][2 * j + 1], af[i], &bf[j][2]);
                }
        }
    }

    const int lr = lane >> 2;
    const int lc = (lane & 3) * 2;
#pragma unroll
    for (int i = 0; i < 2; i++) {
        const size_t row0 = arow0 + wm * 32 + i * 16 + lr;
#pragma unroll
        for (int j = 0; j < 8; j++) {
            const int col = n0blk + wn * 64 + j * 8 + lc;
            const float bx = bias[col], by = bias[col + 1];
            float2 o0 = make_float2(acc[i][j][0] + bx, acc[i][j][1] + by);
            float2 o1 = make_float2(acc[i][j][2] + bx, acc[i][j][3] + by);
            *(float2*)(out + row0 * DIM_ + col) = o0;
            *(float2*)(out + (row0 + 8) * DIM_ + col) = o1;
        }
    }
}

// ---------------------------------------------------------------------------
// Sparse attention (R8 version, unchanged).
// ---------------------------------------------------------------------------
__global__ __launch_bounds__(256)
void attn_kernel(const float* __restrict__ qh, const float* __restrict__ kh,
                 const float* __restrict__ vh, const int* __restrict__ rns,
                 float* __restrict__ out) {
    __shared__ float sq[DIM_];
    __shared__ int srow[TOPK_];
    __shared__ int svrow[TOPK_];
    __shared__ float sscore[NH_][TOPK_];

    const int n = blockIdx.x;
    const int b = blockIdx.y;
    const int tid = threadIdx.x;
    const int lane = tid & 31;
    const int wid = tid >> 5;

    ((float2*)sq)[tid] = ((const float2*)(qh + (size_t)(n * BS_ + b) * DIM_))[tid];
    if (tid < TOPK_)
        srow[tid] = rns[((size_t)b * NP_ + n) * TOPK_ + tid];
    __syncthreads();
    if (tid < TOPK_) {
        const int m = srow[tid];
        bool valid = true;
        for (int j = 0; j < tid; j++)
            if (srow[j] == m) valid = false;
        svrow[tid] = valid ? (m * BS_ + b) : -1;
    }
    __syncthreads();

    // ---- Phase 1: scores (warp w covers candidates w, w+8, w+16, w+24) ----
    const int g = lane >> 4;
#pragma unroll
    for (int cc = 0; cc < 4; cc++) {
        const int c = wid + cc * 8;
        const int r = svrow[c];
        float p[4] = {0.f, 0.f, 0.f, 0.f};
        if (r >= 0) {
            const float4* kp = (const float4*)(kh + (size_t)r * DIM_);
            const float4* qp = (const float4*)sq;
#pragma unroll
            for (int j = 0; j < 4; j++) {
                const float4 kv = kp[j * 32 + lane];
                const float4 qv = qp[j * 32 + lane];
                float a;
                a = kv.x * qv.x;
                a = fmaf(kv.y, qv.y, a);
                a = fmaf(kv.z, qv.z, a);
                a = fmaf(kv.w, qv.w, a);
                p[j] = a;
            }
        }
#pragma unroll
        for (int j = 0; j < 4; j++) {
            p[j] += __shfl_xor_sync(0xffffffffu, p[j], 8);
            p[j] += __shfl_xor_sync(0xffffffffu, p[j], 4);
            p[j] += __shfl_xor_sync(0xffffffffu, p[j], 2);
            p[j] += __shfl_xor_sync(0xffffffffu, p[j], 1);
        }
        if ((lane & 15) == 0) {
#pragma unroll
            for (int j = 0; j < 4; j++)
                sscore[2 * j + g][c] = (r >= 0) ? p[j] * 0.125f : -INFINITY;
        }
    }
    __syncthreads();

    // ---- Phase 2: per-head softmax ----
    const int h = wid;
    const float s = sscore[h][lane];
    float mx = s;
#pragma unroll
    for (int o = 16; o; o >>= 1)
        mx = fmaxf(mx, __shfl_xor_sync(0xffffffffu, mx, o));
    float p = (s > -1e30f) ? __expf(s - mx) : 0.f;
    float sum = p;
#pragma unroll
    for (int o = 16; o; o >>= 1)
        sum += __shfl_xor_sync(0xffffffffu, sum, o);
    const float w = p / sum;

    // ---- Phase 3: V accumulate ----
    const int rl = svrow[lane];
    float2 acc2 = make_float2(0.f, 0.f);
#pragma unroll
    for (int t = 0; t < TOPK_; t++) {
        const float wt = __shfl_sync(0xffffffffu, w, t);
        const int r = __shfl_sync(0xffffffffu, rl, t);
        if (r >= 0) {
            const float2 vv =
                *(const float2*)(vh + (size_t)r * DIM_ + h * DH_ + lane * 2);
            acc2.x = fmaf(wt, vv.x, acc2.x);
            acc2.y = fmaf(wt, vv.y, acc2.y);
        }
    }
    *(float2*)(out + (size_t)(n * BS_ + b) * DIM_ + h * DH_ + lane * 2) = acc2;
}

// ---------------------------------------------------------------------------
extern "C" void kernel_launch(void* const* d_in, const int* in_sizes, int n_in,
                              void* d_out, int out_size) {
    const float* q   = (const float*)d_in[0];
    const float* k   = (const float*)d_in[1];
    const float* v   = (const float*)d_in[2];
    const int*   rns = (const int*)d_in[3];
    const float* W1  = (const float*)d_in[4];
    const float* b1  = (const float*)d_in[5];
    const float* W2  = (const float*)d_in[6];
    const float* b2  = (const float*)d_in[7];
    const float* W3  = (const float*)d_in[8];
    const float* b3  = (const float*)d_in[9];
    float* out = (float*)d_out;

    __nv_bfloat16 *ahi, *alo, *whi, *wlo;
    float* proj;
    cudaGetSymbolAddress((void**)&ahi, g_ahi);
    cudaGetSymbolAddress((void**)&alo, g_alo);
    cudaGetSymbolAddress((void**)&whi, g_whi);
    cudaGetSymbolAddress((void**)&wlo, g_wlo);
    cudaGetSymbolAddress((void**)&proj, g_proj);

    cudaFuncSetAttribute(gemm_mma, cudaFuncAttributeMaxDynamicSharedMemorySize,
                         GEMM_SMEM);

    const size_t offK = (size_t)MROWS_Q * DIM_;
    const size_t offV = offK + (size_t)MROWS_KV * DIM_;

    split_all<<<(R_W3 / 2 + 255) / 256, 256>>>(q, k, v, W1, W2, W3,
                                               ahi, alo, whi, wlo);

    gemm_mma<<<dim3(4, 288), 256, GEMM_SMEM>>>(ahi, alo, whi, wlo, b1, b2, b3, proj);

    attn_kernel<<<dim3(NP_, BS_), 256>>>(proj, proj + offK, proj + offV, rns, out);
}

// round 13
// speedup vs baseline: 1.0770x; 1.0081x over previous
#include <cuda_runtime.h>
#include <cuda_bf16.h>
#include <math.h>
#include <stdint.h>

// Problem constants
#define NP_   1024
#define MNP_  4096
#define BS_   4
#define DIM_  512
#define NH_   8
#define DH_   64
#define TOPK_ 32

#define MROWS_Q  (NP_*BS_)                 // 4096
#define MROWS_KV (MNP_*BS_)                // 16384
#define MTOT     (MROWS_Q + 2*MROWS_KV)    // 36864

// ---------------------------------------------------------------------------
// Scratch (device globals; no allocation allowed)
// ---------------------------------------------------------------------------
__device__ __nv_bfloat16 g_ahi[(size_t)MTOT * DIM_];
__device__ __nv_bfloat16 g_alo[(size_t)MTOT * DIM_];
__device__ __nv_bfloat16 g_whi[3 * DIM_ * DIM_];
__device__ __nv_bfloat16 g_wlo[3 * DIM_ * DIM_];
__device__ float         g_proj[(size_t)MTOT * DIM_];

// ---------------------------------------------------------------------------
// Helpers
// ---------------------------------------------------------------------------
__device__ __forceinline__ uint32_t smem_u32(const void* p) {
    uint32_t a;
    asm("{ .reg .u64 t; cvta.to.shared.u64 t, %1; cvt.u32.u64 %0, t; }"
        : "=r"(a) : "l"(p));
    return a;
}

__device__ __forceinline__ void cp16(uint32_t dst, const void* src) {
    asm volatile("cp.async.cg.shared.global [%0], [%1], 16;\n"
                 :: "r"(dst), "l"(src) : "memory");
}

__device__ __forceinline__ uint32_t swz(uint32_t o) { return o ^ ((o >> 3) & 0x70); }

__device__ __forceinline__ void ldsm4(uint32_t* f, uint32_t addr) {
    asm volatile("ldmatrix.sync.aligned.m8n8.x4.shared.b16 {%0,%1,%2,%3}, [%4];"
                 : "=r"(f[0]), "=r"(f[1]), "=r"(f[2]), "=r"(f[3]) : "r"(addr));
}

__device__ __forceinline__ void mma16816(float* d, const uint32_t* a,
                                         const uint32_t* b) {
    asm volatile(
        "mma.sync.aligned.m16n8k16.row.col.f32.bf16.bf16.f32 "
        "{%0,%1,%2,%3}, {%4,%5,%6,%7}, {%8,%9}, {%0,%1,%2,%3};"
        : "+f"(d[0]), "+f"(d[1]), "+f"(d[2]), "+f"(d[3])
        : "r"(a[0]), "r"(a[1]), "r"(a[2]), "r"(a[3]), "r"(b[0]), "r"(b[1]));
}

// ---------------------------------------------------------------------------
// Fused split: fp32 -> (bf16 hi, bf16 lo); unchanged from R8/R11.
// ---------------------------------------------------------------------------
#define R_Q  (MROWS_Q * DIM_ / 4)
#define R_K  (R_Q + MROWS_KV * DIM_ / 4)
#define R_V  (R_K + MROWS_KV * DIM_ / 4)
#define R_W1 (R_V + DIM_ * DIM_ / 4)
#define R_W2 (R_W1 + DIM_ * DIM_ / 4)
#define R_W3 (R_W2 + DIM_ * DIM_ / 4)

__global__ __launch_bounds__(256)
void split_all(const float* __restrict__ q, const float* __restrict__ k,
               const float* __restrict__ v, const float* __restrict__ W1,
               const float* __restrict__ W2, const float* __restrict__ W3,
               __nv_bfloat16* __restrict__ ahi, __nv_bfloat16* __restrict__ alo,
               __nv_bfloat16* __restrict__ whi, __nv_bfloat16* __restrict__ wlo) {
    const int i = (blockIdx.x * 256 + threadIdx.x) * 2;   // float4 index
    if (i >= R_W3) return;
    const float* src;
    __nv_bfloat16 *dh, *dl;
    size_t si, di;
    if (i < R_V) {
        di = (size_t)i;
        dh = ahi; dl = alo;
        if (i < R_Q)      { src = q; si = (size_t)i; }
        else if (i < R_K) { src = k; si = (size_t)(i - R_Q); }
        else              { src = v; si = (size_t)(i - R_K); }
    } else {
        di = (size_t)(i - R_V);
        dh = whi; dl = wlo;
        if (i < R_W1)      { src = W1; si = (size_t)(i - R_V); }
        else if (i < R_W2) { src = W2; si = (size_t)(i - R_W1); }
        else               { src = W3; si = (size_t)(i - R_W2); }
    }
    float4 x0 = ((const float4*)src)[si];
    float4 x1 = ((const float4*)src)[si + 1];
    float val[8] = {x0.x, x0.y, x0.z, x0.w, x1.x, x1.y, x1.z, x1.w};
    __nv_bfloat16 h[8], l[8];
#pragma unroll
    for (int j = 0; j < 8; j++) {
        h[j] = __float2bfloat16(val[j]);
        l[j] = __float2bfloat16(val[j] - __bfloat162float(h[j]));
    }
    *(uint4*)(dh + 4 * di) = *(uint4*)h;
    *(uint4*)(dl + 4 * di) = *(uint4*)l;
}

// ---------------------------------------------------------------------------
// mma.sync split-bf16 GEMM with superchunk tile sharing.
// Per k-superchunk (KC=64): load 4 tiles {Ahi,Alo,Whi,Wlo} (vs 6 before) and
// compute the 3 products ahi*Whi + ahi*Wlo (PassAB, shared A fragments) and
// alo*Whi (PassC), all into one accumulator.
// A ring: 3 x 16KB, B ring: 4 x 16KB = 112KB; 2 CTAs/SM.
// Group order: g_{4k}=Ahi_k, g_{4k+1}=Whi_k, g_{4k+2}=Wlo_k, g_{4k+3}=Alo_k.
// ---------------------------------------------------------------------------
#define NKK     8
#define TILE_B  16384                       // 128 x 64 bf16
#define GEMM_SMEM (7 * TILE_B)              // 112KB

__global__ __launch_bounds__(256, 2)
void gemm_mma(const __nv_bfloat16* __restrict__ ahi,
              const __nv_bfloat16* __restrict__ alo,
              const __nv_bfloat16* __restrict__ whi,
              const __nv_bfloat16* __restrict__ wlo,
              const float* __restrict__ b1, const float* __restrict__ b2,
              const float* __restrict__ b3, float* __restrict__ out) {
    extern __shared__ __align__(1024) char smem[];
    const uint32_t sbase = smem_u32(smem);
    const uint32_t aS = sbase;                 // 3 slots
    const uint32_t bS = sbase + 3 * TILE_B;    // 4 slots
    const int tid = threadIdx.x;
    const int wid = tid >> 5;
    const int lane = tid & 31;
    const int wm = wid & 3;
    const int wn = wid >> 2;

    const int n0blk = blockIdx.x * 128;
    const int mt = blockIdx.y;
    const int widx = (mt < 32) ? 0 : (mt < 160) ? 1 : 2;
    const float* bias = (widx == 0) ? b1 : (widx == 1) ? b2 : b3;
    const __nv_bfloat16* Whi = whi + (size_t)widx * DIM_ * DIM_;
    const __nv_bfloat16* Wlo = wlo + (size_t)widx * DIM_ * DIM_;
    const size_t arow0 = (size_t)mt * 128;

    float acc[2][8][4];
#pragma unroll
    for (int i = 0; i < 2; i++)
#pragma unroll
        for (int j = 0; j < 8; j++)
#pragma unroll
            for (int r = 0; r < 4; r++) acc[i][j][r] = 0.f;

    // Load one 128x64 bf16 tile (1024 16B units) + commit as one group.
    auto load_tile = [&](const __nv_bfloat16* src, size_t row0, int kk,
                         uint32_t dst) {
#pragma unroll
        for (int i = 0; i < 4; i++) {
            int u = tid + (i << 8);
            int r = u >> 3, j = u & 7;
            cp16(dst + swz(r * 128 + j * 16),
                 src + (row0 + r) * DIM_ + kk * 64 + j * 8);
        }
        asm volatile("cp.async.commit_group;\n" ::: "memory");
    };

    // Prologue: kk=0 tiles in group order Ahi, Whi, Wlo, Alo.
    load_tile(ahi, arow0, 0, aS + 0 * TILE_B);
    load_tile(Whi, (size_t)n0blk, 0, bS + 0 * TILE_B);
    load_tile(Wlo, (size_t)n0blk, 0, bS + 1 * TILE_B);
    load_tile(alo, arow0, 0, aS + 1 * TILE_B);

    const int a_row = wm * 32 + (lane & 15);
    const int a_ch  = (lane >> 4);
    const int b_row = wn * 64 + (lane & 7) + ((lane >> 4) << 3);
    const int b_ch  = ((lane >> 3) & 1);

#pragma unroll 1
    for (int k = 0; k < NKK; ++k) {
        const uint32_t a_hi_s = aS + ((2 * k) % 3) * TILE_B;
        const uint32_t a_lo_s = aS + ((2 * k + 1) % 3) * TILE_B;
        const uint32_t b_hi_s = bS + ((2 * k) & 3) * TILE_B;
        const uint32_t b_lo_s = bS + ((2 * k + 1) & 3) * TILE_B;

        __syncthreads();                     // close prev PassC reads
        if (k < NKK - 1) {                   // top prefetch: Ahi, Whi, Wlo
            load_tile(ahi, arow0, k + 1, aS + ((2 * k + 2) % 3) * TILE_B);
            load_tile(Whi, (size_t)n0blk, k + 1, bS + ((2 * k + 2) & 3) * TILE_B);
            load_tile(Wlo, (size_t)n0blk, k + 1, bS + ((2 * k + 3) & 3) * TILE_B);
            asm volatile("cp.async.wait_group 4;\n" ::: "memory");
        } else {
            asm volatile("cp.async.wait_group 1;\n" ::: "memory");
        }
        __syncthreads();                     // Ahi_k, Whi_k, Wlo_k resident

        // ---- PassAB: ahi x Whi, ahi x Wlo (shared A fragments) ----
#pragma unroll
        for (int ks = 0; ks < 4; ks++) {
            const int c0 = ks * 2;
            uint32_t af[2][4];
#pragma unroll
            for (int i = 0; i < 2; i++)
                ldsm4(af[i], a_hi_s + swz((a_row + i * 16) * 128 + (c0 + a_ch) * 16));
            uint32_t bf[4][4];
#pragma unroll
            for (int j = 0; j < 4; j++)
                ldsm4(bf[j], b_hi_s + swz((b_row + j * 16) * 128 + (c0 + b_ch) * 16));
#pragma unroll
            for (int i = 0; i < 2; i++)
#pragma unroll
                for (int j = 0; j < 4; j++) {
                    mma16816(acc[i][2 * j],     af[i], &bf[j][0]);
                    mma16816(acc[i][2 * j + 1], af[i], &bf[j][2]);
                }
#pragma unroll
            for (int j = 0; j < 4; j++)
                ldsm4(bf[j], b_lo_s + swz((b_row + j * 16) * 128 + (c0 + b_ch) * 16));
#pragma unroll
            for (int i = 0; i < 2; i++)
#pragma unroll
                for (int j = 0; j < 4; j++) {
                    mma16816(acc[i][2 * j],     af[i], &bf[j][0]);
                    mma16816(acc[i][2 * j + 1], af[i], &bf[j][2]);
                }
        }

        // Alo_k ready + free Ahi_k's slot for Alo_{k+1}
        if (k < NKK - 1)
            asm volatile("cp.async.wait_group 3;\n" ::: "memory");
        else
            asm volatile("cp.async.wait_group 0;\n" ::: "memory");
        __syncthreads();
        if (k < NKK - 1)
            load_tile(alo, arow0, k + 1, aS + ((2 * k + 3) % 3) * TILE_B);

        // ---- PassC: alo x Whi ----
#pragma unroll
        for (int ks = 0; ks < 4; ks++) {
            const int c0 = ks * 2;
            uint32_t af[2][4];
#pragma unroll
            for (int i = 0; i < 2; i++)
                ldsm4(af[i], a_lo_s + swz((a_row + i * 16) * 128 + (c0 + a_ch) * 16));
            uint32_t bf[4][4];
#pragma unroll
            for (int j = 0; j < 4; j++)
                ldsm4(bf[j], b_hi_s + swz((b_row + j * 16) * 128 + (c0 + b_ch) * 16));
#pragma unroll
            for (int i = 0; i < 2; i++)
#pragma unroll
                for (int j = 0; j < 4; j++) {
                    mma16816(acc[i][2 * j],     af[i], &bf[j][0]);
                    mma16816(acc[i][2 * j + 1], af[i], &bf[j][2]);
                }
        }
    }

    // epilogue: acc[i][j] is m16n8 at rows (wm*32+i*16), cols (wn*64+j*8)
    const int lr = lane >> 2;
    const int lc = (lane & 3) * 2;
#pragma unroll
    for (int i = 0; i < 2; i++) {
        const size_t row0 = arow0 + wm * 32 + i * 16 + lr;
#pragma unroll
        for (int j = 0; j < 8; j++) {
            const int col = n0blk + wn * 64 + j * 8 + lc;
            const float bx = bias[col], by = bias[col + 1];
            float2 o0 = make_float2(acc[i][j][0] + bx, acc[i][j][1] + by);
            float2 o1 = make_float2(acc[i][j][2] + bx, acc[i][j][3] + by);
            *(float2*)(out + row0 * DIM_ + col) = o0;
            *(float2*)(out + (row0 + 8) * DIM_ + col) = o1;
        }
    }
}

// ---------------------------------------------------------------------------
// Sparse attention (R8 version, unchanged).
// ---------------------------------------------------------------------------
__global__ __launch_bounds__(256)
void attn_kernel(const float* __restrict__ qh, const float* __restrict__ kh,
                 const float* __restrict__ vh, const int* __restrict__ rns,
                 float* __restrict__ out) {
    __shared__ float sq[DIM_];
    __shared__ int srow[TOPK_];
    __shared__ int svrow[TOPK_];
    __shared__ float sscore[NH_][TOPK_];

    const int n = blockIdx.x;
    const int b = blockIdx.y;
    const int tid = threadIdx.x;
    const int lane = tid & 31;
    const int wid = tid >> 5;

    ((float2*)sq)[tid] = ((const float2*)(qh + (size_t)(n * BS_ + b) * DIM_))[tid];
    if (tid < TOPK_)
        srow[tid] = rns[((size_t)b * NP_ + n) * TOPK_ + tid];
    __syncthreads();
    if (tid < TOPK_) {
        const int m = srow[tid];
        bool valid = true;
        for (int j = 0; j < tid; j++)
            if (srow[j] == m) valid = false;
        svrow[tid] = valid ? (m * BS_ + b) : -1;
    }
    __syncthreads();

    const int g = lane >> 4;
#pragma unroll
    for (int cc = 0; cc < 4; cc++) {
        const int c = wid + cc * 8;
        const int r = svrow[c];
        float p[4] = {0.f, 0.f, 0.f, 0.f};
        if (r >= 0) {
            const float4* kp = (const float4*)(kh + (size_t)r * DIM_);
            const float4* qp = (const float4*)sq;
#pragma unroll
            for (int j = 0; j < 4; j++) {
                const float4 kv = kp[j * 32 + lane];
                const float4 qv = qp[j * 32 + lane];
                float a;
                a = kv.x * qv.x;
                a = fmaf(kv.y, qv.y, a);
                a = fmaf(kv.z, qv.z, a);
                a = fmaf(kv.w, qv.w, a);
                p[j] = a;
            }
        }
#pragma unroll
        for (int j = 0; j < 4; j++) {
            p[j] += __shfl_xor_sync(0xffffffffu, p[j], 8);
            p[j] += __shfl_xor_sync(0xffffffffu, p[j], 4);
            p[j] += __shfl_xor_sync(0xffffffffu, p[j], 2);
            p[j] += __shfl_xor_sync(0xffffffffu, p[j], 1);
        }
        if ((lane & 15) == 0) {
#pragma unroll
            for (int j = 0; j < 4; j++)
                sscore[2 * j + g][c] = (r >= 0) ? p[j] * 0.125f : -INFINITY;
        }
    }
    __syncthreads();

    const int h = wid;
    const float s = sscore[h][lane];
    float mx = s;
#pragma unroll
    for (int o = 16; o; o >>= 1)
        mx = fmaxf(mx, __shfl_xor_sync(0xffffffffu, mx, o));
    float p = (s > -1e30f) ? __expf(s - mx) : 0.f;
    float sum = p;
#pragma unroll
    for (int o = 16; o; o >>= 1)
        sum += __shfl_xor_sync(0xffffffffu, sum, o);
    const float w = p / sum;

    const int rl = svrow[lane];
    float2 acc2 = make_float2(0.f, 0.f);
#pragma unroll
    for (int t = 0; t < TOPK_; t++) {
        const float wt = __shfl_sync(0xffffffffu, w, t);
        const int r = __shfl_sync(0xffffffffu, rl, t);
        if (r >= 0) {
            const float2 vv =
                *(const float2*)(vh + (size_t)r * DIM_ + h * DH_ + lane * 2);
            acc2.x = fmaf(wt, vv.x, acc2.x);
            acc2.y = fmaf(wt, vv.y, acc2.y);
        }
    }
    *(float2*)(out + (size_t)(n * BS_ + b) * DIM_ + h * DH_ + lane * 2) = acc2;
}

// ---------------------------------------------------------------------------
extern "C" void kernel_launch(void* const* d_in, const int* in_sizes, int n_in,
                              void* d_out, int out_size) {
    const float* q   = (const float*)d_in[0];
    const float* k   = (const float*)d_in[1];
    const float* v   = (const float*)d_in[2];
    const int*   rns = (const int*)d_in[3];
    const float* W1  = (const float*)d_in[4];
    const float* b1  = (const float*)d_in[5];
    const float* W2  = (const float*)d_in[6];
    const float* b2  = (const float*)d_in[7];
    const float* W3  = (const float*)d_in[8];
    const float* b3  = (const float*)d_in[9];
    float* out = (float*)d_out;

    __nv_bfloat16 *ahi, *alo, *whi, *wlo;
    float* proj;
    cudaGetSymbolAddress((void**)&ahi, g_ahi);
    cudaGetSymbolAddress((void**)&alo, g_alo);
    cudaGetSymbolAddress((void**)&whi, g_whi);
    cudaGetSymbolAddress((void**)&wlo, g_wlo);
    cudaGetSymbolAddress((void**)&proj, g_proj);

    cudaFuncSetAttribute(gemm_mma, cudaFuncAttributeMaxDynamicSharedMemorySize,
                         GEMM_SMEM);

    const size_t offK = (size_t)MROWS_Q * DIM_;
    const size_t offV = offK + (size_t)MROWS_KV * DIM_;

    split_all<<<(R_W3 / 2 + 255) / 256, 256>>>(q, k, v, W1, W2, W3,
                                               ahi, alo, whi, wlo);

    gemm_mma<<<dim3(4, 288), 256, GEMM_SMEM>>>(ahi, alo, whi, wlo, b1, b2, b3, proj);

    attn_kernel<<<dim3(NP_, BS_), 256>>>(proj, proj + offK, proj + offV, rns, out);
}

// round 15
// speedup vs baseline: 1.1286x; 1.0479x over previous
#include <cuda_runtime.h>
#include <cuda_bf16.h>
#include <math.h>
#include <stdint.h>

// Problem constants
#define NP_   1024
#define MNP_  4096
#define BS_   4
#define DIM_  512
#define NH_   8
#define DH_   64
#define TOPK_ 32

#define MROWS_Q  (NP_*BS_)                 // 4096
#define MROWS_KV (MNP_*BS_)                // 16384
#define MTOT     (MROWS_Q + 2*MROWS_KV)    // 36864

// ---------------------------------------------------------------------------
// Scratch (device global; no allocation allowed)
// ---------------------------------------------------------------------------
__device__ float g_proj[(size_t)MTOT * DIM_];

// ---------------------------------------------------------------------------
// Helpers
// ---------------------------------------------------------------------------
__device__ __forceinline__ uint32_t smem_u32(const void* p) {
    uint32_t a;
    asm("{ .reg .u64 t; cvta.to.shared.u64 t, %1; cvt.u32.u64 %0, t; }"
        : "=r"(a) : "l"(p));
    return a;
}

__device__ __forceinline__ void cp16(uint32_t dst, const void* src) {
    asm volatile("cp.async.cg.shared.global [%0], [%1], 16;\n"
                 :: "r"(dst), "l"(src) : "memory");
}

__device__ __forceinline__ uint32_t swz(uint32_t o) { return o ^ ((o >> 3) & 0x70); }

// Load fp32 from smem and round-to-nearest to tf32 (RNA — required; HW
// truncation of raw fp32 bits would add a ~1e-3 systematic bias).
__device__ __forceinline__ uint32_t ld_tf32(uint32_t addr) {
    float f;
    asm volatile("ld.shared.f32 %0, [%1];" : "=f"(f) : "r"(addr));
    uint32_t r;
    asm("cvt.rna.tf32.f32 %0, %1;" : "=r"(r) : "f"(f));
    return r;
}

__device__ __forceinline__ void mma_tf32(float* d, const uint32_t* a,
                                         const uint32_t* b) {
    asm volatile(
        "mma.sync.aligned.m16n8k8.row.col.f32.tf32.tf32.f32 "
        "{%0,%1,%2,%3}, {%4,%5,%6,%7}, {%8,%9}, {%0,%1,%2,%3};"
        : "+f"(d[0]), "+f"(d[1]), "+f"(d[2]), "+f"(d[3])
        : "r"(a[0]), "r"(a[1]), "r"(a[2]), "r"(a[3]), "r"(b[0]), "r"(b[1]));
}

// ---------------------------------------------------------------------------
// Single-pass TF32 GEMM: out[m][n] = sum_k A[m][k] * W[n][k] + bias[n]
// A = q|k|v fp32 inputs directly (no preprocessing). CTA tile 128x128,
// K-chunk 32 fp32 (128B rows, SW128), 16 chunks, 3-stage cp.async pipeline.
// 8 warps as 4(m) x 2(n): warp tile 32x64; mma.m16n8k8.tf32.
// ---------------------------------------------------------------------------
#define KC       32
#define NCHUNK   16
#define STAGES   3
#define A_BYTES  (128 * 128)                 // 128 rows x 32 f32
#define B_BYTES  (128 * 128)
#define STG_B    (A_BYTES + B_BYTES)         // 32KB
#define GEMM_SMEM (STAGES * STG_B)           // 96KB

__global__ __launch_bounds__(256, 2)
void gemm_tf32(const float* __restrict__ q, const float* __restrict__ k,
               const float* __restrict__ v,
               const float* __restrict__ W1, const float* __restrict__ W2,
               const float* __restrict__ W3,
               const float* __restrict__ b1, const float* __restrict__ b2,
               const float* __restrict__ b3, float* __restrict__ out) {
    extern __shared__ __align__(1024) char smem[];
    const uint32_t sbase = smem_u32(smem);
    const int tid = threadIdx.x;
    const int wid = tid >> 5;
    const int lane = tid & 31;
    const int wm = wid & 3;
    const int wn = wid >> 2;

    const int n0blk = blockIdx.x * 128;
    const int mt = blockIdx.y;
    // region select: A source + local row base + weight/bias
    const float* Abase;
    size_t arow_loc;
    const float* Wp;
    const float* bias;
    if (mt < 32)       { Abase = q; arow_loc = (size_t)mt * 128;        Wp = W1; bias = b1; }
    else if (mt < 160) { Abase = k; arow_loc = (size_t)(mt - 32) * 128;  Wp = W2; bias = b2; }
    else               { Abase = v; arow_loc = (size_t)(mt - 160) * 128; Wp = W3; bias = b3; }
    const size_t orow0 = (size_t)mt * 128;   // output row base (q|k|v concat)

    float acc[2][8][4];
#pragma unroll
    for (int i = 0; i < 2; i++)
#pragma unroll
        for (int j = 0; j < 8; j++)
#pragma unroll
            for (int r = 0; r < 4; r++) acc[i][j][r] = 0.f;

    // chunk c: k-offset c*32 floats. A tile 128x32 f32, B tile 128x32 f32.
    auto load_chunk = [&](int c, int s) {
        const int kk = c * KC;
        const uint32_t a_s = sbase + s * STG_B;
        const uint32_t b_s = a_s + A_BYTES;
#pragma unroll
        for (int i = 0; i < 4; i++) {        // A: 1024 16B units
            int u = tid + (i << 8);
            int r = u >> 3, j = u & 7;       // row, 16B-col (4 floats)
            cp16(a_s + swz(r * 128 + j * 16),
                 Abase + (arow_loc + r) * DIM_ + kk + j * 4);
        }
#pragma unroll
        for (int i = 0; i < 4; i++) {        // B: 1024 16B units
            int u = tid + (i << 8);
            int r = u >> 3, j = u & 7;
            cp16(b_s + swz(r * 128 + j * 16),
                 Wp + (size_t)(n0blk + r) * DIM_ + kk + j * 4);
        }
        asm volatile("cp.async.commit_group;\n" ::: "memory");
    };

    load_chunk(0, 0);
    load_chunk(1, 1);

    const int fr = lane >> 2;    // 0..7
    const int fc = lane & 3;     // 0..3

#pragma unroll 1
    for (int c = 0; c < NCHUNK; ++c) {
        const int s = c % STAGES;
        if (c == NCHUNK - 1)
            asm volatile("cp.async.wait_group 0;\n" ::: "memory");
        else
            asm volatile("cp.async.wait_group 1;\n" ::: "memory");
        __syncthreads();
        if (c + 2 < NCHUNK) load_chunk(c + 2, (c + 2) % STAGES);

        const uint32_t a_s = sbase + s * STG_B;
        const uint32_t b_s = a_s + A_BYTES;
#pragma unroll
        for (int ks = 0; ks < 4; ks++) {
            const int c0 = ks * 8;           // k offset within chunk (floats)
            // A fragments: m-tile i at rows wm*32 + i*16
            uint32_t af[2][4];
#pragma unroll
            for (int i = 0; i < 2; i++) {
                const int rb = wm * 32 + i * 16 + fr;
                af[i][0] = ld_tf32(a_s + swz(rb * 128 + (c0 + fc) * 4));
                af[i][1] = ld_tf32(a_s + swz((rb + 8) * 128 + (c0 + fc) * 4));
                af[i][2] = ld_tf32(a_s + swz(rb * 128 + (c0 + fc + 4) * 4));
                af[i][3] = ld_tf32(a_s + swz((rb + 8) * 128 + (c0 + fc + 4) * 4));
            }
            // B fragments: n-tile j at cols wn*64 + j*8
            uint32_t bf[8][2];
#pragma unroll
            for (int j = 0; j < 8; j++) {
                const int nb = wn * 64 + j * 8 + fr;
                bf[j][0] = ld_tf32(b_s + swz(nb * 128 + (c0 + fc) * 4));
                bf[j][1] = ld_tf32(b_s + swz(nb * 128 + (c0 + fc + 4) * 4));
            }
#pragma unroll
            for (int i = 0; i < 2; i++)
#pragma unroll
                for (int j = 0; j < 8; j++)
                    mma_tf32(acc[i][j], af[i], bf[j]);
        }
    }

    // epilogue: acc[i][j] is m16n8 at rows (wm*32+i*16), cols (wn*64+j*8)
    const int lr = lane >> 2;
    const int lc = (lane & 3) * 2;
#pragma unroll
    for (int i = 0; i < 2; i++) {
        const size_t row0 = orow0 + wm * 32 + i * 16 + lr;
#pragma unroll
        for (int j = 0; j < 8; j++) {
            const int col = n0blk + wn * 64 + j * 8 + lc;
            const float bx = bias[col], by = bias[col + 1];
            float2 o0 = make_float2(acc[i][j][0] + bx, acc[i][j][1] + by);
            float2 o1 = make_float2(acc[i][j][2] + bx, acc[i][j][3] + by);
            *(float2*)(out + row0 * DIM_ + col) = o0;
            *(float2*)(out + (row0 + 8) * DIM_ + col) = o1;
        }
    }
}

// ---------------------------------------------------------------------------
// Sparse attention (R8 version, unchanged).
// ---------------------------------------------------------------------------
__global__ __launch_bounds__(256)
void attn_kernel(const float* __restrict__ qh, const float* __restrict__ kh,
                 const float* __restrict__ vh, const int* __restrict__ rns,
                 float* __restrict__ out) {
    __shared__ float sq[DIM_];
    __shared__ int srow[TOPK_];
    __shared__ int svrow[TOPK_];
    __shared__ float sscore[NH_][TOPK_];

    const int n = blockIdx.x;
    const int b = blockIdx.y;
    const int tid = threadIdx.x;
    const int lane = tid & 31;
    const int wid = tid >> 5;

    ((float2*)sq)[tid] = ((const float2*)(qh + (size_t)(n * BS_ + b) * DIM_))[tid];
    if (tid < TOPK_)
        srow[tid] = rns[((size_t)b * NP_ + n) * TOPK_ + tid];
    __syncthreads();
    if (tid < TOPK_) {
        const int m = srow[tid];
        bool valid = true;
        for (int j = 0; j < tid; j++)
            if (srow[j] == m) valid = false;
        svrow[tid] = valid ? (m * BS_ + b) : -1;
    }
    __syncthreads();

    const int g = lane >> 4;
#pragma unroll
    for (int cc = 0; cc < 4; cc++) {
        const int c = wid + cc * 8;
        const int r = svrow[c];
        float p[4] = {0.f, 0.f, 0.f, 0.f};
        if (r >= 0) {
            const float4* kp = (const float4*)(kh + (size_t)r * DIM_);
            const float4* qp = (const float4*)sq;
#pragma unroll
            for (int j = 0; j < 4; j++) {
                const float4 kv = kp[j * 32 + lane];
                const float4 qv = qp[j * 32 + lane];
                float a;
                a = kv.x * qv.x;
                a = fmaf(kv.y, qv.y, a);
                a = fmaf(kv.z, qv.z, a);
                a = fmaf(kv.w, qv.w, a);
                p[j] = a;
            }
        }
#pragma unroll
        for (int j = 0; j < 4; j++) {
            p[j] += __shfl_xor_sync(0xffffffffu, p[j], 8);
            p[j] += __shfl_xor_sync(0xffffffffu, p[j], 4);
            p[j] += __shfl_xor_sync(0xffffffffu, p[j], 2);
            p[j] += __shfl_xor_sync(0xffffffffu, p[j], 1);
        }
        if ((lane & 15) == 0) {
#pragma unroll
            for (int j = 0; j < 4; j++)
                sscore[2 * j + g][c] = (r >= 0) ? p[j] * 0.125f : -INFINITY;
        }
    }
    __syncthreads();

    const int h = wid;
    const float s = sscore[h][lane];
    float mx = s;
#pragma unroll
    for (int o = 16; o; o >>= 1)
        mx = fmaxf(mx, __shfl_xor_sync(0xffffffffu, mx, o));
    float p = (s > -1e30f) ? __expf(s - mx) : 0.f;
    float sum = p;
#pragma unroll
    for (int o = 16; o; o >>= 1)
        sum += __shfl_xor_sync(0xffffffffu, sum, o);
    const float w = p / sum;

    const int rl = svrow[lane];
    float2 acc2 = make_float2(0.f, 0.f);
#pragma unroll
    for (int t = 0; t < TOPK_; t++) {
        const float wt = __shfl_sync(0xffffffffu, w, t);
        const int r = __shfl_sync(0xffffffffu, rl, t);
        if (r >= 0) {
            const float2 vv =
                *(const float2*)(vh + (size_t)r * DIM_ + h * DH_ + lane * 2);
            acc2.x = fmaf(wt, vv.x, acc2.x);
            acc2.y = fmaf(wt, vv.y, acc2.y);
        }
    }
    *(float2*)(out + (size_t)(n * BS_ + b) * DIM_ + h * DH_ + lane * 2) = acc2;
}

// ---------------------------------------------------------------------------
extern "C" void kernel_launch(void* const* d_in, const int* in_sizes, int n_in,
                              void* d_out, int out_size) {
    const float* q   = (const float*)d_in[0];
    const float* k   = (const float*)d_in[1];
    const float* v   = (const float*)d_in[2];
    const int*   rns = (const int*)d_in[3];
    const float* W1  = (const float*)d_in[4];
    const float* b1  = (const float*)d_in[5];
    const float* W2  = (const float*)d_in[6];
    const float* b2  = (const float*)d_in[7];
    const float* W3  = (const float*)d_in[8];
    const float* b3  = (const float*)d_in[9];
    float* out = (float*)d_out;

    float* proj;
    cudaGetSymbolAddress((void**)&proj, g_proj);

    cudaFuncSetAttribute(gemm_tf32, cudaFuncAttributeMaxDynamicSharedMemorySize,
                         GEMM_SMEM);

    const size_t offK = (size_t)MROWS_Q * DIM_;
    const size_t offV = offK + (size_t)MROWS_KV * DIM_;

    gemm_tf32<<<dim3(4, 288), 256, GEMM_SMEM>>>(q, k, v, W1, W2, W3,
                                                b1, b2, b3, proj);

    attn_kernel<<<dim3(NP_, BS_), 256>>>(proj, proj + offK, proj + offV, rns, out);
}

// round 16
// speedup vs baseline: 1.7984x; 1.5934x over previous
#include <cuda_runtime.h>
#include <cuda_fp16.h>
#include <math.h>
#include <stdint.h>

// Problem constants
#define NP_   1024
#define MNP_  4096
#define BS_   4
#define DIM_  512
#define NH_   8
#define DH_   64
#define TOPK_ 32

#define MROWS_Q  (NP_*BS_)                 // 4096
#define MROWS_KV (MNP_*BS_)                // 16384
#define MTOT     (MROWS_Q + 2*MROWS_KV)    // 36864

// ---------------------------------------------------------------------------
// Scratch (device globals; no allocation allowed)
// ---------------------------------------------------------------------------
__device__ __half g_a16[(size_t)MTOT * DIM_];      // q|k|v rows in fp16
__device__ __half g_w16[3 * DIM_ * DIM_];          // W1|W2|W3 in fp16
__device__ float  g_proj[(size_t)MTOT * DIM_];

// ---------------------------------------------------------------------------
// Helpers
// ---------------------------------------------------------------------------
__device__ __forceinline__ uint32_t smem_u32(const void* p) {
    uint32_t a;
    asm("{ .reg .u64 t; cvta.to.shared.u64 t, %1; cvt.u32.u64 %0, t; }"
        : "=r"(a) : "l"(p));
    return a;
}

__device__ __forceinline__ void cp16(uint32_t dst, const void* src) {
    asm volatile("cp.async.cg.shared.global [%0], [%1], 16;\n"
                 :: "r"(dst), "l"(src) : "memory");
}

__device__ __forceinline__ uint32_t swz(uint32_t o) { return o ^ ((o >> 3) & 0x70); }

__device__ __forceinline__ void ldsm4(uint32_t* f, uint32_t addr) {
    asm volatile("ldmatrix.sync.aligned.m8n8.x4.shared.b16 {%0,%1,%2,%3}, [%4];"
                 : "=r"(f[0]), "=r"(f[1]), "=r"(f[2]), "=r"(f[3]) : "r"(addr));
}

__device__ __forceinline__ void mma16816(float* d, const uint32_t* a,
                                         const uint32_t* b) {
    asm volatile(
        "mma.sync.aligned.m16n8k16.row.col.f32.f16.f16.f32 "
        "{%0,%1,%2,%3}, {%4,%5,%6,%7}, {%8,%9}, {%0,%1,%2,%3};"
        : "+f"(d[0]), "+f"(d[1]), "+f"(d[2]), "+f"(d[3])
        : "r"(a[0]), "r"(a[1]), "r"(a[2]), "r"(a[3]), "r"(b[0]), "r"(b[1]));
}

// ---------------------------------------------------------------------------
// Convert fp32 -> fp16 (RN): q|k|v -> g_a16, W1|W2|W3 -> g_w16.
// Each thread handles 8 floats (2 float4 in, 1 uint4 out).
// ---------------------------------------------------------------------------
#define R_Q  (MROWS_Q * DIM_ / 4)
#define R_K  (R_Q + MROWS_KV * DIM_ / 4)
#define R_V  (R_K + MROWS_KV * DIM_ / 4)
#define R_W1 (R_V + DIM_ * DIM_ / 4)
#define R_W2 (R_W1 + DIM_ * DIM_ / 4)
#define R_W3 (R_W2 + DIM_ * DIM_ / 4)             // 4915200 float4 total

__global__ __launch_bounds__(256)
void cvt_half(const float* __restrict__ q, const float* __restrict__ k,
              const float* __restrict__ v, const float* __restrict__ W1,
              const float* __restrict__ W2, const float* __restrict__ W3,
              __half* __restrict__ a16, __half* __restrict__ w16) {
    const int i = (blockIdx.x * 256 + threadIdx.x) * 2;   // float4 index
    if (i >= R_W3) return;
    const float* src;
    __half* dst;
    size_t si, di;
    if (i < R_V) {
        di = (size_t)i;
        dst = a16;
        if (i < R_Q)      { src = q; si = (size_t)i; }
        else if (i < R_K) { src = k; si = (size_t)(i - R_Q); }
        else              { src = v; si = (size_t)(i - R_K); }
    } else {
        di = (size_t)(i - R_V);
        dst = w16;
        if (i < R_W1)      { src = W1; si = (size_t)(i - R_V); }
        else if (i < R_W2) { src = W2; si = (size_t)(i - R_W1); }
        else               { src = W3; si = (size_t)(i - R_W2); }
    }
    float4 x0 = ((const float4*)src)[si];
    float4 x1 = ((const float4*)src)[si + 1];
    float val[8] = {x0.x, x0.y, x0.z, x0.w, x1.x, x1.y, x1.z, x1.w};
    __half h[8];
#pragma unroll
    for (int j = 0; j < 8; j++) h[j] = __float2half_rn(val[j]);
    *(uint4*)(dst + 4 * di) = *(uint4*)h;
}

// ---------------------------------------------------------------------------
// Single-pass fp16 GEMM (R8 pipeline skeleton): out = A*W^T + bias.
// CTA tile 128x128, K-chunk 64 halves (SW128), 8 chunks, 3-stage cp.async.
// 8 warps as 4(m) x 2(n): warp tile 32x64.
// ---------------------------------------------------------------------------
#define KC       64
#define NCHUNK   8
#define STAGES   3
#define A_BYTES  (128 * 128)
#define B_BYTES  (128 * 128)
#define STG_B    (A_BYTES + B_BYTES)
#define GEMM_SMEM (STAGES * STG_B)           // 96KB

__global__ __launch_bounds__(256, 2)
void gemm_f16(const __half* __restrict__ a16, const __half* __restrict__ w16,
              const float* __restrict__ b1, const float* __restrict__ b2,
              const float* __restrict__ b3, float* __restrict__ out) {
    extern __shared__ __align__(1024) char smem[];
    const uint32_t sbase = smem_u32(smem);
    const int tid = threadIdx.x;
    const int wid = tid >> 5;
    const int lane = tid & 31;
    const int wm = wid & 3;
    const int wn = wid >> 2;

    const int n0blk = blockIdx.x * 128;
    const int mt = blockIdx.y;
    const int widx = (mt < 32) ? 0 : (mt < 160) ? 1 : 2;
    const float* bias = (widx == 0) ? b1 : (widx == 1) ? b2 : b3;
    const __half* Wp = w16 + (size_t)widx * DIM_ * DIM_;
    const size_t arow0 = (size_t)mt * 128;

    float acc[2][8][4];
#pragma unroll
    for (int i = 0; i < 2; i++)
#pragma unroll
        for (int j = 0; j < 8; j++)
#pragma unroll
            for (int r = 0; r < 4; r++) acc[i][j][r] = 0.f;

    auto load_chunk = [&](int c, int s) {
        const int kk = c * KC;
        const uint32_t a_s = sbase + s * STG_B;
        const uint32_t b_s = a_s + A_BYTES;
#pragma unroll
        for (int i = 0; i < 4; i++) {
            int u = tid + (i << 8);
            int r = u >> 3, j = u & 7;
            cp16(a_s + swz(r * 128 + j * 16),
                 a16 + (arow0 + r) * DIM_ + kk + j * 8);
        }
#pragma unroll
        for (int i = 0; i < 4; i++) {
            int u = tid + (i << 8);
            int r = u >> 3, j = u & 7;
            cp16(b_s + swz(r * 128 + j * 16),
                 Wp + (size_t)(n0blk + r) * DIM_ + kk + j * 8);
        }
        asm volatile("cp.async.commit_group;\n" ::: "memory");
    };

    load_chunk(0, 0);
    load_chunk(1, 1);

    const int a_row = wm * 32 + (lane & 15);
    const int a_ch  = (lane >> 4);
    const int b_row = wn * 64 + (lane & 7) + ((lane >> 4) << 3);
    const int b_ch  = ((lane >> 3) & 1);

#pragma unroll 1
    for (int c = 0; c < NCHUNK; ++c) {
        const int s = c % STAGES;
        if (c == NCHUNK - 1)
            asm volatile("cp.async.wait_group 0;\n" ::: "memory");
        else
            asm volatile("cp.async.wait_group 1;\n" ::: "memory");
        __syncthreads();
        if (c + 2 < NCHUNK) load_chunk(c + 2, (c + 2) % STAGES);

        const uint32_t a_s = sbase + s * STG_B;
        const uint32_t b_s = a_s + A_BYTES;
#pragma unroll
        for (int ks = 0; ks < 4; ks++) {
            const int c0 = ks * 2;
            uint32_t af[2][4];
#pragma unroll
            for (int i = 0; i < 2; i++)
                ldsm4(af[i], a_s + swz((a_row + i * 16) * 128 + (c0 + a_ch) * 16));
            uint32_t bf[4][4];
#pragma unroll
            for (int j = 0; j < 4; j++)
                ldsm4(bf[j], b_s + swz((b_row + j * 16) * 128 + (c0 + b_ch) * 16));
#pragma unroll
            for (int i = 0; i < 2; i++)
#pragma unroll
                for (int j = 0; j < 4; j++) {
                    mma16816(acc[i][2 * j],     af[i], &bf[j][0]);
                    mma16816(acc[i][2 * j + 1], af[i], &bf[j][2]);
                }
        }
    }

    // epilogue: acc[i][j] is m16n8 at rows (wm*32+i*16), cols (wn*64+j*8)
    const int lr = lane >> 2;
    const int lc = (lane & 3) * 2;
#pragma unroll
    for (int i = 0; i < 2; i++) {
        const size_t row0 = arow0 + wm * 32 + i * 16 + lr;
#pragma unroll
        for (int j = 0; j < 8; j++) {
            const int col = n0blk + wn * 64 + j * 8 + lc;
            const float bx = bias[col], by = bias[col + 1];
            float2 o0 = make_float2(acc[i][j][0] + bx, acc[i][j][1] + by);
            float2 o1 = make_float2(acc[i][j][2] + bx, acc[i][j][3] + by);
            *(float2*)(out + row0 * DIM_ + col) = o0;
            *(float2*)(out + (row0 + 8) * DIM_ + col) = o1;
        }
    }
}

// ---------------------------------------------------------------------------
// Sparse attention (R8 version, unchanged).
// ---------------------------------------------------------------------------
__global__ __launch_bounds__(256)
void attn_kernel(const float* __restrict__ qh, const float* __restrict__ kh,
                 const float* __restrict__ vh, const int* __restrict__ rns,
                 float* __restrict__ out) {
    __shared__ float sq[DIM_];
    __shared__ int srow[TOPK_];
    __shared__ int svrow[TOPK_];
    __shared__ float sscore[NH_][TOPK_];

    const int n = blockIdx.x;
    const int b = blockIdx.y;
    const int tid = threadIdx.x;
    const int lane = tid & 31;
    const int wid = tid >> 5;

    ((float2*)sq)[tid] = ((const float2*)(qh + (size_t)(n * BS_ + b) * DIM_))[tid];
    if (tid < TOPK_)
        srow[tid] = rns[((size_t)b * NP_ + n) * TOPK_ + tid];
    __syncthreads();
    if (tid < TOPK_) {
        const int m = srow[tid];
        bool valid = true;
        for (int j = 0; j < tid; j++)
            if (srow[j] == m) valid = false;
        svrow[tid] = valid ? (m * BS_ + b) : -1;
    }
    __syncthreads();

    const int g = lane >> 4;
#pragma unroll
    for (int cc = 0; cc < 4; cc++) {
        const int c = wid + cc * 8;
        const int r = svrow[c];
        float p[4] = {0.f, 0.f, 0.f, 0.f};
        if (r >= 0) {
            const float4* kp = (const float4*)(kh + (size_t)r * DIM_);
            const float4* qp = (const float4*)sq;
#pragma unroll
            for (int j = 0; j < 4; j++) {
                const float4 kv = kp[j * 32 + lane];
                const float4 qv = qp[j * 32 + lane];
                float a;
                a = kv.x * qv.x;
                a = fmaf(kv.y, qv.y, a);
                a = fmaf(kv.z, qv.z, a);
                a = fmaf(kv.w, qv.w, a);
                p[j] = a;
            }
        }
#pragma unroll
        for (int j = 0; j < 4; j++) {
            p[j] += __shfl_xor_sync(0xffffffffu, p[j], 8);
            p[j] += __shfl_xor_sync(0xffffffffu, p[j], 4);
            p[j] += __shfl_xor_sync(0xffffffffu, p[j], 2);
            p[j] += __shfl_xor_sync(0xffffffffu, p[j], 1);
        }
        if ((lane & 15) == 0) {
#pragma unroll
            for (int j = 0; j < 4; j++)
                sscore[2 * j + g][c] = (r >= 0) ? p[j] * 0.125f : -INFINITY;
        }
    }
    __syncthreads();

    const int h = wid;
    const float s = sscore[h][lane];
    float mx = s;
#pragma unroll
    for (int o = 16; o; o >>= 1)
        mx = fmaxf(mx, __shfl_xor_sync(0xffffffffu, mx, o));
    float p = (s > -1e30f) ? __expf(s - mx) : 0.f;
    float sum = p;
#pragma unroll
    for (int o = 16; o; o >>= 1)
        sum += __shfl_xor_sync(0xffffffffu, sum, o);
    const float w = p / sum;

    const int rl = svrow[lane];
    float2 acc2 = make_float2(0.f, 0.f);
#pragma unroll
    for (int t = 0; t < TOPK_; t++) {
        const float wt = __shfl_sync(0xffffffffu, w, t);
        const int r = __shfl_sync(0xffffffffu, rl, t);
        if (r >= 0) {
            const float2 vv =
                *(const float2*)(vh + (size_t)r * DIM_ + h * DH_ + lane * 2);
            acc2.x = fmaf(wt, vv.x, acc2.x);
            acc2.y = fmaf(wt, vv.y, acc2.y);
        }
    }
    *(float2*)(out + (size_t)(n * BS_ + b) * DIM_ + h * DH_ + lane * 2) = acc2;
}

// ---------------------------------------------------------------------------
extern "C" void kernel_launch(void* const* d_in, const int* in_sizes, int n_in,
                              void* d_out, int out_size) {
    const float* q   = (const float*)d_in[0];
    const float* k   = (const float*)d_in[1];
    const float* v   = (const float*)d_in[2];
    const int*   rns = (const int*)d_in[3];
    const float* W1  = (const float*)d_in[4];
    const float* b1  = (const float*)d_in[5];
    const float* W2  = (const float*)d_in[6];
    const float* b2  = (const float*)d_in[7];
    const float* W3  = (const float*)d_in[8];
    const float* b3  = (const float*)d_in[9];
    float* out = (float*)d_out;

    __half *a16, *w16;
    float* proj;
    cudaGetSymbolAddress((void**)&a16, g_a16);
    cudaGetSymbolAddress((void**)&w16, g_w16);
    cudaGetSymbolAddress((void**)&proj, g_proj);

    cudaFuncSetAttribute(gemm_f16, cudaFuncAttributeMaxDynamicSharedMemorySize,
                         GEMM_SMEM);

    const size_t offK = (size_t)MROWS_Q * DIM_;
    const size_t offV = offK + (size_t)MROWS_KV * DIM_;

    cvt_half<<<(R_W3 / 2 + 255) / 256, 256>>>(q, k, v, W1, W2, W3, a16, w16);

    gemm_f16<<<dim3(4, 288), 256, GEMM_SMEM>>>(a16, w16, b1, b2, b3, proj);

    attn_kernel<<<dim3(NP_, BS_), 256>>>(proj, proj + offK, proj + offV, rns, out);
}